// round 1
// baseline (speedup 1.0000x reference)
#include <cuda_runtime.h>
#include <math.h>

// Problem constants (fixed by the benchmark's setup_inputs)
#define B_  8
#define N_  4096
#define K_  1024
#define D_  256

// Tiling
#define TM  128      // rows (points) per block
#define TN  128      // cols (centers) per K-tile
#define BK  32       // D-chunk per smem stage
#define PAD_LD 132   // padded leading dim (floats) for As/Bs: 132%32==4 -> conflict-free transpose stores; 132*4%16==0 keeps float4 alignment

// Scratch (no device allocation allowed -> __device__ globals)
__device__ float g_psq[B_ * N_];
__device__ float g_csq[B_ * K_];
__device__ float g_partial[(N_ / TM) * B_];   // 32*8 = 256 block partial sums

// ---------------------------------------------------------------------------
// Kernel 1: squared norms of every point row and center row (warp per row)
// ---------------------------------------------------------------------------
__global__ void sqnorm_kernel(const float* __restrict__ points,
                              const float* __restrict__ centers) {
    int warp = (blockIdx.x * blockDim.x + threadIdx.x) >> 5;
    int lane = threadIdx.x & 31;
    const int nP   = B_ * N_;
    const int nTot = nP + B_ * K_;
    if (warp >= nTot) return;

    const float* src = (warp < nP) ? (points + (size_t)warp * D_)
                                   : (centers + (size_t)(warp - nP) * D_);
    const float4* v = (const float4*)src;   // inputs are 16B-aligned (cudaMalloc'd)
    float s = 0.f;
#pragma unroll
    for (int i = 0; i < 2; i++) {           // 256 floats / 32 lanes = 2 float4 each
        float4 x = v[lane + i * 32];
        s += x.x * x.x + x.y * x.y + x.z * x.z + x.w * x.w;
    }
#pragma unroll
    for (int o = 16; o > 0; o >>= 1) s += __shfl_xor_sync(0xffffffffu, s, o);
    if (lane == 0) {
        if (warp < nP) g_psq[warp] = s;
        else           g_csq[warp - nP] = s;
    }
}

// ---------------------------------------------------------------------------
// Kernel 2: fused GEMM + min-over-centers.
// Block = (128 points) x (all 1024 centers, in 128-wide tiles) for one batch.
// Thread microtile 8x8. min is kept in d^2 space (sqrt is monotone).
// ---------------------------------------------------------------------------
__global__ void __launch_bounds__(256, 2)
center_min_kernel(const float* __restrict__ points,
                  const float* __restrict__ centers) {
    __shared__ float As[BK * PAD_LD];       // As[d][row]
    __shared__ float Bs[BK * PAD_LD];       // Bs[d][col]
    __shared__ float red[TM * 17];          // min-reduction across tx
    __shared__ float sdist[TM];             // per-row distances -> block sum

    const int b       = blockIdx.y;
    const int rowBase = blockIdx.x * TM;
    const int tid     = threadIdx.x;
    const int tx      = tid & 15;           // 16 thread-cols
    const int ty      = tid >> 4;           // 16 thread-rows

    const float* Pb = points  + ((size_t)b * N_ + rowBase) * D_;
    const float* Cb = centers + (size_t)b * K_ * D_;

    float runmin[8];
#pragma unroll
    for (int i = 0; i < 8; i++) runmin[i] = 3.4e38f;

    float psq[8];
#pragma unroll
    for (int i = 0; i < 8; i++) psq[i] = g_psq[b * N_ + rowBase + ty * 8 + i];

    for (int kt = 0; kt < K_; kt += TN) {
        float acc[8][8];
#pragma unroll
        for (int i = 0; i < 8; i++)
#pragma unroll
            for (int j = 0; j < 8; j++) acc[i][j] = 0.f;

        for (int dk = 0; dk < D_; dk += BK) {
            __syncthreads();
            // Stage A and B chunks: 128 rows x 32 floats = 1024 float4 each,
            // 4 float4 per thread, transposed into [d][row] layout.
#pragma unroll
            for (int l = 0; l < 4; l++) {
                int idx = tid + l * 256;
                int r   = idx >> 3;         // 0..127
                int c4  = idx & 7;          // float4 index within the 32-wide chunk
                float4 v = *(const float4*)(Pb + (size_t)r * D_ + dk + c4 * 4);
                As[(c4 * 4 + 0) * PAD_LD + r] = v.x;
                As[(c4 * 4 + 1) * PAD_LD + r] = v.y;
                As[(c4 * 4 + 2) * PAD_LD + r] = v.z;
                As[(c4 * 4 + 3) * PAD_LD + r] = v.w;
                float4 w = *(const float4*)(Cb + (size_t)(kt + r) * D_ + dk + c4 * 4);
                Bs[(c4 * 4 + 0) * PAD_LD + r] = w.x;
                Bs[(c4 * 4 + 1) * PAD_LD + r] = w.y;
                Bs[(c4 * 4 + 2) * PAD_LD + r] = w.z;
                Bs[(c4 * 4 + 3) * PAD_LD + r] = w.w;
            }
            __syncthreads();

#pragma unroll 8
            for (int d = 0; d < BK; d++) {
                float a[8], bb[8];
                *(float4*)&a[0]  = *(const float4*)&As[d * PAD_LD + ty * 8];
                *(float4*)&a[4]  = *(const float4*)&As[d * PAD_LD + ty * 8 + 4];
                *(float4*)&bb[0] = *(const float4*)&Bs[d * PAD_LD + tx * 8];
                *(float4*)&bb[4] = *(const float4*)&Bs[d * PAD_LD + tx * 8 + 4];
#pragma unroll
                for (int i = 0; i < 8; i++)
#pragma unroll
                    for (int j = 0; j < 8; j++)
                        acc[i][j] = fmaf(a[i], bb[j], acc[i][j]);
            }
        }

        // d2 = psq + csq - 2*cross ; fold into running min
#pragma unroll
        for (int j = 0; j < 8; j++) {
            float csq = g_csq[b * K_ + kt + tx * 8 + j];
#pragma unroll
            for (int i = 0; i < 8; i++) {
                float d2 = psq[i] + csq - 2.f * acc[i][j];
                runmin[i] = fminf(runmin[i], d2);
            }
        }
    }

    // Reduce min across the 16 thread-columns, then sqrt, then block sum.
    __syncthreads();
#pragma unroll
    for (int i = 0; i < 8; i++) red[(ty * 8 + i) * 17 + tx] = runmin[i];
    __syncthreads();

    if (tid < TM) {
        float m = red[tid * 17];
#pragma unroll
        for (int t = 1; t < 16; t++) m = fminf(m, red[tid * 17 + t]);
        sdist[tid] = sqrtf(fmaxf(m, 0.f));
    }
    __syncthreads();
    for (int s = 64; s > 0; s >>= 1) {
        if (tid < s) sdist[tid] += sdist[tid + s];
        __syncthreads();
    }
    if (tid == 0)
        g_partial[blockIdx.y * gridDim.x + blockIdx.x] = sdist[0];
}

// ---------------------------------------------------------------------------
// Kernel 3: deterministic final reduction of 256 block partials -> mean
// ---------------------------------------------------------------------------
__global__ void final_reduce_kernel(float* __restrict__ out) {
    __shared__ float s[256];
    int tid = threadIdx.x;
    s[tid] = g_partial[tid];                // exactly 256 partials
    __syncthreads();
    for (int st = 128; st > 0; st >>= 1) {
        if (tid < st) s[tid] += s[tid + st];
        __syncthreads();
    }
    if (tid == 0) out[0] = s[0] / (float)(B_ * N_);
}

// ---------------------------------------------------------------------------
extern "C" void kernel_launch(void* const* d_in, const int* in_sizes, int n_in,
                              void* d_out, int out_size) {
    const float* points  = (const float*)d_in[0];
    const float* centers = (const float*)d_in[1];

    // 1) squared norms: (8*4096 + 8*1024) = 40960 warps -> 5120 blocks of 256
    sqnorm_kernel<<<5120, 256>>>(points, centers);

    // 2) fused GEMM + min: grid (N/TM, B) = (32, 8)
    center_min_kernel<<<dim3(N_ / TM, B_), 256>>>(points, centers);

    // 3) mean
    final_reduce_kernel<<<1, 256>>>((float*)d_out);
}

// round 3
// speedup vs baseline: 6.0245x; 6.0245x over previous
#include <cuda_runtime.h>
#include <cuda_bf16.h>
#include <math.h>
#include <stdint.h>

// Problem constants
#define B_  8
#define N_  4096
#define K_  1024
#define D_  256

// Tiling
#define TM   128         // rows per CTA
#define TNT  128         // centers per N-tile
#define NT   8           // N-tiles per CTA (all 1024 centers)
#define BK   64          // D-chunk per B stage
#define NCHUNK 32        // NT * (D_/BK)

// ---------------- device scratch (no allocation allowed) -------------------
__device__ __align__(16) __nv_bfloat16 g_pb[(size_t)B_ * N_ * D_];
__device__ __align__(16) __nv_bfloat16 g_cb[(size_t)B_ * K_ * D_];
__device__ float g_psq[B_ * N_];
__device__ float g_csq[B_ * K_];
__device__ float g_partial[(N_ / TM) * B_];

// ---------------- SMEM layout (dynamic) -------------------------------------
#define SM_CSQ  0                 // float[1024]           4096 B
#define SM_ARR  4096              // float[4][128]         2048 B
#define SM_SUM  6144              // float[128]             512 B
#define SM_A    8192              // 128 rows x 512 B     65536 B
#define SM_B    (8192 + 65536)    // 2 x 16384 B          32768 B
#define SMEM_TOTAL (SM_B + 2 * 16384)

// ---------------- PTX helpers ----------------------------------------------
__device__ __forceinline__ uint32_t smem_u32(const void* p) {
    uint32_t a;
    asm("{ .reg .u64 t; cvta.to.shared.u64 t, %1; cvt.u32.u64 %0, t; }" : "=r"(a) : "l"(p));
    return a;
}
__device__ __forceinline__ void cpasync16(uint32_t dst, const void* src) {
    asm volatile("cp.async.cg.shared.global [%0], [%1], 16;" :: "r"(dst), "l"(src));
}
__device__ __forceinline__ void cp_commit() { asm volatile("cp.async.commit_group;" ::: "memory"); }
template <int N> __device__ __forceinline__ void cp_wait() {
    asm volatile("cp.async.wait_group %0;" :: "n"(N) : "memory");
}
__device__ __forceinline__ void ldsm4(uint32_t* r, uint32_t addr) {
    asm volatile("ldmatrix.sync.aligned.m8n8.x4.shared.b16 {%0,%1,%2,%3}, [%4];"
                 : "=r"(r[0]), "=r"(r[1]), "=r"(r[2]), "=r"(r[3]) : "r"(addr));
}
__device__ __forceinline__ void mma16816(float* c, const uint32_t* a, uint32_t b0, uint32_t b1) {
    asm volatile(
        "mma.sync.aligned.m16n8k16.row.col.f32.bf16.bf16.f32 "
        "{%0,%1,%2,%3}, {%4,%5,%6,%7}, {%8,%9}, {%0,%1,%2,%3};"
        : "+f"(c[0]), "+f"(c[1]), "+f"(c[2]), "+f"(c[3])
        : "r"(a[0]), "r"(a[1]), "r"(a[2]), "r"(a[3]), "r"(b0), "r"(b1));
}

// ---------------------------------------------------------------------------
// Kernel 1: fp32 -> bf16 conversion fused with squared norms (warp per row)
// ---------------------------------------------------------------------------
__global__ void convert_kernel(const float* __restrict__ points,
                               const float* __restrict__ centers) {
    int warp = (blockIdx.x * blockDim.x + threadIdx.x) >> 5;
    int lane = threadIdx.x & 31;
    const int nP = B_ * N_;
    if (warp >= nP + B_ * K_) return;

    const float* src;
    __nv_bfloat16* dst;
    float* sq;
    if (warp < nP) { src = points + (size_t)warp * D_;  dst = g_pb + (size_t)warp * D_;  sq = &g_psq[warp]; }
    else { int w = warp - nP; src = centers + (size_t)w * D_; dst = g_cb + (size_t)w * D_; sq = &g_csq[w]; }

    float s = 0.f;
#pragma unroll
    for (int i = 0; i < 2; i++) {
        float4 x = ((const float4*)src)[lane + i * 32];
        s += x.x * x.x + x.y * x.y + x.z * x.z + x.w * x.w;
        __nv_bfloat162 h0 = __nv_bfloat162(__float2bfloat16_rn(x.x), __float2bfloat16_rn(x.y));
        __nv_bfloat162 h1 = __nv_bfloat162(__float2bfloat16_rn(x.z), __float2bfloat16_rn(x.w));
        ((__nv_bfloat162*)dst)[(lane + i * 32) * 2 + 0] = h0;
        ((__nv_bfloat162*)dst)[(lane + i * 32) * 2 + 1] = h1;
    }
#pragma unroll
    for (int o = 16; o > 0; o >>= 1) s += __shfl_xor_sync(0xffffffffu, s, o);
    if (lane == 0) *sq = s;
}

// ---------------------------------------------------------------------------
// Kernel 2: bf16 HMMA GEMM + fused min over centers.
// One CTA: 128 points x 1024 centers, warps 2(row) x 4(col), warp tile 64x32.
// ---------------------------------------------------------------------------
__device__ __forceinline__ void issue_B(uint32_t sbase, const __nv_bfloat16* Cb,
                                        int g, int tid) {
    int nt = g >> 2, kc = g & 3;
    uint32_t buf = sbase + SM_B + (uint32_t)(g & 1) * 16384;
#pragma unroll
    for (int t = 0; t < 4; t++) {
        int idx = tid + t * 256;           // 0..1023
        int r = idx >> 3, c = idx & 7;     // 128 rows x 8 16B-chunks
        uint32_t dst = buf + (uint32_t)r * 128 + (uint32_t)((c ^ (r & 7)) << 4);
        cpasync16(dst, Cb + (size_t)(nt * TNT + r) * D_ + kc * BK + c * 8);
    }
}

__global__ void __launch_bounds__(256, 2)
center_hmma_kernel() {
    extern __shared__ char smem[];
    const uint32_t sbase = smem_u32(smem);
    const int tid  = threadIdx.x;
    const int lane = tid & 31;
    const int w    = tid >> 5;
    const int wrow = w >> 2;               // 0..1  (64-row half)
    const int wcol = w & 3;                // 0..3  (32-col slice)
    const int b       = blockIdx.y;
    const int rowBase = blockIdx.x * TM;

    const __nv_bfloat16* Pb = g_pb + ((size_t)b * N_ + rowBase) * D_;
    const __nv_bfloat16* Cb = g_cb + (size_t)b * K_ * D_;
    float* csq_s = (float*)(smem + SM_CSQ);
    float* arr   = (float*)(smem + SM_ARR);
    float* ssum  = (float*)(smem + SM_SUM);

    // csq for the whole batch (1024 floats)
#pragma unroll
    for (int i = tid; i < K_; i += 256) csq_s[i] = g_csq[b * K_ + i];

    // A: 128 rows x 256 bf16 (512 B rows, 32 x 16B chunks, XOR swizzle)
#pragma unroll 4
    for (int i = tid; i < 4096; i += 256) {
        int r = i >> 5, c = i & 31;
        uint32_t dst = sbase + SM_A + (uint32_t)r * 512 + (uint32_t)((c ^ (r & 7)) << 4);
        cpasync16(dst, Pb + (size_t)r * D_ + c * 8);
    }
    issue_B(sbase, Cb, 0, tid);
    cp_commit();                            // group: A + B0

    float runmin[8];
#pragma unroll
    for (int i = 0; i < 8; i++) runmin[i] = 3.4e38f;

    float acc[4][4][4];
    const int arow = wrow * 64 + (lane & 15);
    const int brow = wcol * 32 + (lane & 15);
    const int chalf = lane >> 4;

    for (int g = 0; g < NCHUNK; g++) {
        const int nt = g >> 2, kc = g & 3;
        if (kc == 0) {
#pragma unroll
            for (int mf = 0; mf < 4; mf++)
#pragma unroll
                for (int j = 0; j < 4; j++)
#pragma unroll
                    for (int q = 0; q < 4; q++) acc[mf][j][q] = 0.f;
        }

        if (g + 1 < NCHUNK) { issue_B(sbase, Cb, g + 1, tid); cp_commit(); }
        if (g + 1 < NCHUNK) cp_wait<1>(); else cp_wait<0>();
        __syncthreads();                    // chunk g visible to all warps

        const uint32_t Bbuf = sbase + SM_B + (uint32_t)(g & 1) * 16384;
#pragma unroll
        for (int s = 0; s < 4; s++) {
            uint32_t a[4][4];
#pragma unroll
            for (int mf = 0; mf < 4; mf++) {
                int r = arow + mf * 16;
                int c = kc * 8 + s * 2 + chalf;
                ldsm4(a[mf], sbase + SM_A + (uint32_t)r * 512 +
                             (uint32_t)((c ^ (r & 7)) << 4));
            }
            uint32_t bf[2][4];
#pragma unroll
            for (int nf = 0; nf < 2; nf++) {
                int r = brow + nf * 16;
                int c = s * 2 + chalf;
                ldsm4(bf[nf], Bbuf + (uint32_t)r * 128 +
                              (uint32_t)((c ^ (r & 7)) << 4));
            }
#pragma unroll
            for (int mf = 0; mf < 4; mf++)
#pragma unroll
                for (int nf = 0; nf < 2; nf++) {
                    mma16816(acc[mf][nf * 2 + 0], a[mf], bf[nf][0], bf[nf][2]);
                    mma16816(acc[mf][nf * 2 + 1], a[mf], bf[nf][1], bf[nf][3]);
                }
        }

        if (kc == 3) {
            // fold min(csq - 2*cross) for this N-tile
#pragma unroll
            for (int j = 0; j < 4; j++) {
                int nf = j >> 1, hn = j & 1;
                int n0 = nt * TNT + wcol * 32 + nf * 16 + hn * 8 + (lane & 3) * 2;
                float cs0 = csq_s[n0], cs1 = csq_s[n0 + 1];
#pragma unroll
                for (int mf = 0; mf < 4; mf++) {
                    float* c = acc[mf][j];
                    runmin[mf * 2 + 0] = fminf(runmin[mf * 2 + 0],
                                               fminf(cs0 - 2.f * c[0], cs1 - 2.f * c[1]));
                    runmin[mf * 2 + 1] = fminf(runmin[mf * 2 + 1],
                                               fminf(cs0 - 2.f * c[2], cs1 - 2.f * c[3]));
                }
            }
        }
        __syncthreads();                    // all warps done with buf before reuse
    }

    // min across the 4 lanes of each quad (they hold different n columns)
#pragma unroll
    for (int i = 0; i < 8; i++) {
        float v = runmin[i];
        v = fminf(v, __shfl_xor_sync(0xffffffffu, v, 1));
        v = fminf(v, __shfl_xor_sync(0xffffffffu, v, 2));
        runmin[i] = v;
    }
    if ((lane & 3) == 0) {
#pragma unroll
        for (int mf = 0; mf < 4; mf++)
#pragma unroll
            for (int rh = 0; rh < 2; rh++) {
                int row = wrow * 64 + mf * 16 + (lane >> 2) + rh * 8;
                arr[wcol * 128 + row] = runmin[mf * 2 + rh];
            }
    }
    __syncthreads();

    if (tid < TM) {
        float m = fminf(fminf(arr[tid], arr[128 + tid]),
                        fminf(arr[256 + tid], arr[384 + tid]));
        float d2 = g_psq[b * N_ + rowBase + tid] + m;
        ssum[tid] = sqrtf(fmaxf(d2, 0.f));
    }
    __syncthreads();
    for (int s = 64; s > 0; s >>= 1) {
        if (tid < s) ssum[tid] += ssum[tid + s];
        __syncthreads();
    }
    if (tid == 0) g_partial[blockIdx.y * gridDim.x + blockIdx.x] = ssum[0];
}

// ---------------------------------------------------------------------------
// Kernel 3: deterministic final mean over 256 block partials
// ---------------------------------------------------------------------------
__global__ void final_reduce_kernel(float* __restrict__ out) {
    __shared__ float s[256];
    int tid = threadIdx.x;
    s[tid] = g_partial[tid];
    __syncthreads();
    for (int st = 128; st > 0; st >>= 1) {
        if (tid < st) s[tid] += s[tid + st];
        __syncthreads();
    }
    if (tid == 0) out[0] = s[0] / (float)(B_ * N_);
}

// ---------------------------------------------------------------------------
extern "C" void kernel_launch(void* const* d_in, const int* in_sizes, int n_in,
                              void* d_out, int out_size) {
    const float* points  = (const float*)d_in[0];
    const float* centers = (const float*)d_in[1];

    cudaFuncSetAttribute(center_hmma_kernel,
                         cudaFuncAttributeMaxDynamicSharedMemorySize, SMEM_TOTAL);

    convert_kernel<<<5120, 256>>>(points, centers);
    center_hmma_kernel<<<dim3(N_ / TM, B_), 256, SMEM_TOTAL>>>();
    final_reduce_kernel<<<1, 256>>>((float*)d_out);
}

// round 4
// speedup vs baseline: 6.1944x; 1.0282x over previous
#include <cuda_runtime.h>
#include <cuda_bf16.h>
#include <math.h>
#include <stdint.h>

// Problem constants
#define B_  8
#define N_  4096
#define K_  1024
#define D_  256

// Tiling
#define TM   128         // rows per CTA
#define TNT  128         // centers per N-tile
#define NT   8           // N-tiles per CTA
#define BK   64          // D-chunk per B stage
#define NCHUNK 32        // NT * (D_/BK)
#define THREADS 128      // 4 warps, 2x2 warp grid, warp tile 64x64

// ---------------- device scratch (no allocation allowed) -------------------
__device__ __align__(16) __nv_bfloat16 g_pb[(size_t)B_ * N_ * D_];
__device__ __align__(16) __nv_bfloat16 g_cb[(size_t)B_ * K_ * D_];
__device__ float g_psq[B_ * N_];
__device__ float g_csq[B_ * K_];
__device__ float g_partial[(N_ / TM) * B_];       // 256 partials
__device__ unsigned int g_cnt = 0;                // last-CTA counter (reset each run)

// ---------------- SMEM layout (dynamic) -------------------------------------
#define SM_CSQ  0                 // float[1024]          4096 B
#define SM_ARR  4096              // float[2][128]        1024 B
#define SM_SUM  5120              // float[128]            512 B
#define SM_FLAG 5632              // int                     4 B
#define SM_A    8192              // 128 rows x 512 B    65536 B
#define SM_B    (8192 + 65536)    // 2 x 16384 B         32768 B
#define SMEM_TOTAL (SM_B + 2 * 16384)

// ---------------- PTX helpers ----------------------------------------------
__device__ __forceinline__ uint32_t smem_u32(const void* p) {
    uint32_t a;
    asm("{ .reg .u64 t; cvta.to.shared.u64 t, %1; cvt.u32.u64 %0, t; }" : "=r"(a) : "l"(p));
    return a;
}
__device__ __forceinline__ void cpasync16(uint32_t dst, const void* src) {
    asm volatile("cp.async.cg.shared.global [%0], [%1], 16;" :: "r"(dst), "l"(src));
}
__device__ __forceinline__ void cp_commit() { asm volatile("cp.async.commit_group;" ::: "memory"); }
template <int N> __device__ __forceinline__ void cp_wait() {
    asm volatile("cp.async.wait_group %0;" :: "n"(N) : "memory");
}
__device__ __forceinline__ void ldsm4(uint32_t* r, uint32_t addr) {
    asm volatile("ldmatrix.sync.aligned.m8n8.x4.shared.b16 {%0,%1,%2,%3}, [%4];"
                 : "=r"(r[0]), "=r"(r[1]), "=r"(r[2]), "=r"(r[3]) : "r"(addr));
}
__device__ __forceinline__ void mma16816(float* c, const uint32_t* a, uint32_t b0, uint32_t b1) {
    asm volatile(
        "mma.sync.aligned.m16n8k16.row.col.f32.bf16.bf16.f32 "
        "{%0,%1,%2,%3}, {%4,%5,%6,%7}, {%8,%9}, {%0,%1,%2,%3};"
        : "+f"(c[0]), "+f"(c[1]), "+f"(c[2]), "+f"(c[3])
        : "r"(a[0]), "r"(a[1]), "r"(a[2]), "r"(a[3]), "r"(b0), "r"(b1));
}

// ---------------------------------------------------------------------------
// Kernel 1: fp32 -> bf16 conversion fused with squared norms (warp per row)
// ---------------------------------------------------------------------------
__global__ void convert_kernel(const float* __restrict__ points,
                               const float* __restrict__ centers) {
    int warp = (blockIdx.x * blockDim.x + threadIdx.x) >> 5;
    int lane = threadIdx.x & 31;
    const int nP = B_ * N_;
    if (warp >= nP + B_ * K_) return;

    const float* src;
    __nv_bfloat16* dst;
    float* sq;
    if (warp < nP) { src = points + (size_t)warp * D_;  dst = g_pb + (size_t)warp * D_;  sq = &g_psq[warp]; }
    else { int w = warp - nP; src = centers + (size_t)w * D_; dst = g_cb + (size_t)w * D_; sq = &g_csq[w]; }

    float s = 0.f;
#pragma unroll
    for (int i = 0; i < 2; i++) {
        float4 x = ((const float4*)src)[lane + i * 32];
        s += x.x * x.x + x.y * x.y + x.z * x.z + x.w * x.w;
        __nv_bfloat162 h0 = __floats2bfloat162_rn(x.x, x.y);
        __nv_bfloat162 h1 = __floats2bfloat162_rn(x.z, x.w);
        uint2 u;
        u.x = *reinterpret_cast<uint32_t*>(&h0);
        u.y = *reinterpret_cast<uint32_t*>(&h1);
        ((uint2*)dst)[lane + i * 32] = u;
    }
#pragma unroll
    for (int o = 16; o > 0; o >>= 1) s += __shfl_xor_sync(0xffffffffu, s, o);
    if (lane == 0) *sq = s;
}

// ---------------------------------------------------------------------------
// Kernel 2: bf16 HMMA GEMM + fused min + fused final mean.
// CTA: 128 points x 1024 centers. 4 warps (2 row x 2 col), warp tile 64x64.
// ---------------------------------------------------------------------------
__device__ __forceinline__ void issue_B(uint32_t sbase, const __nv_bfloat16* Cb,
                                        int g, int tid) {
    int nt = g >> 2, kc = g & 3;
    uint32_t buf = sbase + SM_B + (uint32_t)(g & 1) * 16384;
#pragma unroll
    for (int t = 0; t < 8; t++) {
        int idx = tid + t * THREADS;       // 0..1023
        int r = idx >> 3, c = idx & 7;     // 128 rows x 8 16B-chunks
        uint32_t dst = buf + (uint32_t)r * 128 + (uint32_t)((c ^ (r & 7)) << 4);
        cpasync16(dst, Cb + (size_t)(nt * TNT + r) * D_ + kc * BK + c * 8);
    }
}

__global__ void __launch_bounds__(THREADS, 2)
center_hmma_kernel(float* __restrict__ out) {
    extern __shared__ char smem[];
    const uint32_t sbase = smem_u32(smem);
    const int tid  = threadIdx.x;
    const int lane = tid & 31;
    const int w    = tid >> 5;
    const int wrow = w >> 1;               // 0..1  (64-row half)
    const int wcol = w & 1;                // 0..1  (64-col half)
    const int b       = blockIdx.y;
    const int rowBase = blockIdx.x * TM;

    const __nv_bfloat16* Pb = g_pb + ((size_t)b * N_ + rowBase) * D_;
    const __nv_bfloat16* Cb = g_cb + (size_t)b * K_ * D_;
    float* csq_s = (float*)(smem + SM_CSQ);
    float* arr   = (float*)(smem + SM_ARR);
    float* ssum  = (float*)(smem + SM_SUM);
    int*   flag  = (int*)(smem + SM_FLAG);

    // csq for the whole batch (1024 floats)
#pragma unroll
    for (int i = tid; i < K_; i += THREADS) csq_s[i] = g_csq[b * K_ + i];

    // A: 128 rows x 256 bf16 (512 B rows, 32 x 16B chunks, XOR swizzle)
#pragma unroll 8
    for (int i = tid; i < 4096; i += THREADS) {
        int r = i >> 5, c = i & 31;
        uint32_t dst = sbase + SM_A + (uint32_t)r * 512 + (uint32_t)((c ^ (r & 7)) << 4);
        cpasync16(dst, Pb + (size_t)r * D_ + c * 8);
    }
    issue_B(sbase, Cb, 0, tid);
    cp_commit();                            // group: A + B0

    float runmin[8];
#pragma unroll
    for (int i = 0; i < 8; i++) runmin[i] = 3.4e38f;

    float acc[4][8][4];                     // mfrag x (8-col group) x quad
    const int arow  = wrow * 64 + (lane & 15);
    const int brow  = wcol * 64 + (lane & 15);
    const int chalf = lane >> 4;

    for (int g = 0; g < NCHUNK; g++) {
        const int nt = g >> 2, kc = g & 3;
        if (kc == 0) {
#pragma unroll
            for (int mf = 0; mf < 4; mf++)
#pragma unroll
                for (int j = 0; j < 8; j++)
#pragma unroll
                    for (int q = 0; q < 4; q++) acc[mf][j][q] = 0.f;
        }

        if (g + 1 < NCHUNK) { issue_B(sbase, Cb, g + 1, tid); cp_commit(); }
        if (g + 1 < NCHUNK) cp_wait<1>(); else cp_wait<0>();
        __syncthreads();                    // chunk g visible to all warps

        const uint32_t Bbuf = sbase + SM_B + (uint32_t)(g & 1) * 16384;
#pragma unroll
        for (int s = 0; s < 4; s++) {
            uint32_t a[4][4];
#pragma unroll
            for (int mf = 0; mf < 4; mf++) {
                int r = arow + mf * 16;
                int c = kc * 8 + s * 2 + chalf;
                ldsm4(a[mf], sbase + SM_A + (uint32_t)r * 512 +
                             (uint32_t)((c ^ (r & 7)) << 4));
            }
            uint32_t bf[4][4];
#pragma unroll
            for (int nf = 0; nf < 4; nf++) {
                int r = brow + nf * 16;
                int c = s * 2 + chalf;
                ldsm4(bf[nf], Bbuf + (uint32_t)r * 128 +
                              (uint32_t)((c ^ (r & 7)) << 4));
            }
#pragma unroll
            for (int mf = 0; mf < 4; mf++)
#pragma unroll
                for (int nf = 0; nf < 4; nf++) {
                    mma16816(acc[mf][nf * 2 + 0], a[mf], bf[nf][0], bf[nf][2]);
                    mma16816(acc[mf][nf * 2 + 1], a[mf], bf[nf][1], bf[nf][3]);
                }
        }

        if (kc == 3) {
            // fold min(csq - 2*cross) for this N-tile
#pragma unroll
            for (int j = 0; j < 8; j++) {
                int n0 = nt * TNT + wcol * 64 + (j >> 1) * 16 + (j & 1) * 8 + (lane & 3) * 2;
                float cs0 = csq_s[n0], cs1 = csq_s[n0 + 1];
#pragma unroll
                for (int mf = 0; mf < 4; mf++) {
                    float* c = acc[mf][j];
                    runmin[mf * 2 + 0] = fminf(runmin[mf * 2 + 0],
                                               fminf(cs0 - 2.f * c[0], cs1 - 2.f * c[1]));
                    runmin[mf * 2 + 1] = fminf(runmin[mf * 2 + 1],
                                               fminf(cs0 - 2.f * c[2], cs1 - 2.f * c[3]));
                }
            }
        }
        __syncthreads();                    // all warps done with buf before reuse
    }

    // min across the 4 lanes of each quad (different n columns)
#pragma unroll
    for (int i = 0; i < 8; i++) {
        float v = runmin[i];
        v = fminf(v, __shfl_xor_sync(0xffffffffu, v, 1));
        v = fminf(v, __shfl_xor_sync(0xffffffffu, v, 2));
        runmin[i] = v;
    }
    if ((lane & 3) == 0) {
#pragma unroll
        for (int mf = 0; mf < 4; mf++)
#pragma unroll
            for (int rh = 0; rh < 2; rh++) {
                int row = wrow * 64 + mf * 16 + (lane >> 2) + rh * 8;
                arr[wcol * 128 + row] = runmin[mf * 2 + rh];
            }
    }
    __syncthreads();

    if (tid < TM) {
        float m  = fminf(arr[tid], arr[128 + tid]);
        float d2 = g_psq[b * N_ + rowBase + tid] + m;
        ssum[tid] = sqrtf(fmaxf(d2, 0.f));
    }
    __syncthreads();
    for (int s = 64; s > 0; s >>= 1) {
        if (tid < s && tid + s < TM) ssum[tid] += ssum[tid + s];
        __syncthreads();
    }
    if (tid == 0) {
        g_partial[blockIdx.y * gridDim.x + blockIdx.x] = ssum[0];
        __threadfence();
        unsigned old = atomicAdd(&g_cnt, 1u);
        *flag = (old == (unsigned)(gridDim.x * gridDim.y - 1));
    }
    __syncthreads();

    // Last CTA: deterministic fixed-order reduction of the 256 partials.
    if (*flag) {
        float v = g_partial[tid] + g_partial[tid + 128];
        ssum[tid] = v;
        __syncthreads();
        for (int s = 64; s > 0; s >>= 1) {
            if (tid < s) ssum[tid] += ssum[tid + s];
            __syncthreads();
        }
        if (tid == 0) {
            out[0] = ssum[0] / (float)(B_ * N_);
            g_cnt = 0;                      // reset for next graph replay
        }
    }
}

// ---------------------------------------------------------------------------
extern "C" void kernel_launch(void* const* d_in, const int* in_sizes, int n_in,
                              void* d_out, int out_size) {
    const float* points  = (const float*)d_in[0];
    const float* centers = (const float*)d_in[1];

    cudaFuncSetAttribute(center_hmma_kernel,
                         cudaFuncAttributeMaxDynamicSharedMemorySize, SMEM_TOTAL);

    convert_kernel<<<5120, 256>>>(points, centers);
    center_hmma_kernel<<<dim3(N_ / TM, B_), THREADS, SMEM_TOTAL>>>((float*)d_out);
}